// round 12
// baseline (speedup 1.0000x reference)
#include <cuda_runtime.h>
#include <cstdint>

__device__ double g_accum = 0.0;
__device__ unsigned int g_done_count = 0;

__device__ __forceinline__ unsigned long long mk_evict_last_policy() {
    unsigned long long pol;
    asm volatile("createpolicy.fractional.L2::evict_last.b64 %0, 1.0;" : "=l"(pol));
    return pol;
}
__device__ __forceinline__ float4 ldg_persist4(const float4* p, unsigned long long pol) {
    float4 v;
    asm volatile("ld.global.L2::cache_hint.v4.f32 {%0,%1,%2,%3}, [%4], %5;"
                 : "=f"(v.x), "=f"(v.y), "=f"(v.z), "=f"(v.w)
                 : "l"(p), "l"(pol));
    return v;
}
__device__ __forceinline__ int ldg_persist_s32(const int* p, unsigned long long pol) {
    int v;
    asm volatile("ld.global.L2::cache_hint.s32 %0, [%1], %2;"
                 : "=r"(v) : "l"(p), "l"(pol));
    return v;
}
__device__ __forceinline__ long long ldg_persist_s64(const long long* p, unsigned long long pol) {
    long long v;
    asm volatile("ld.global.L2::cache_hint.s64 %0, [%1], %2;"
                 : "=l"(v) : "l"(p), "l"(pol));
    return v;
}
// release-scoped counter increment: orders the preceding accum atomic
__device__ __forceinline__ unsigned int atom_inc_release(unsigned int* p) {
    unsigned int prev;
    asm volatile("atom.add.release.gpu.global.u32 %0, [%1], 1;"
                 : "=r"(prev) : "l"(p) : "memory");
    return prev;
}
__device__ __forceinline__ double ld_acquire_f64(const double* p) {
    double v;
    asm volatile("ld.acquire.gpu.global.f64 %0, [%1];"
                 : "=d"(v) : "l"(p) : "memory");
    return v;
}

// One warp per row, transposed mapping across 148 SMs, all loads evict_last.
// SYNC-FREE TAIL: per-warp atomicAdd + release counter; globally-last warp
// finalizes. No __syncthreads anywhere.
__global__ void __launch_bounds__(896, 1)
center_loss_fused(const float* __restrict__ x,
                  const float* __restrict__ centers,
                  const int* __restrict__ labels_raw,
                  float* __restrict__ out,
                  int B, int D, int C) {
    const int lane = threadIdx.x & 31;
    const int warp_in_blk = threadIdx.x >> 5;
    const int warps_per_blk = blockDim.x >> 5;
    const int nwarps = gridDim.x * warps_per_blk;
    const int n4 = D >> 2;

    const unsigned long long pol = mk_evict_last_policy();

    // dtype probe once per warp, resolved once (independent of row data)
    int nsample = B < 32 ? B : 32;
    int probe = (lane < nsample) ? ldg_persist_s32(labels_raw + 2 * lane + 1, pol) : 0;
    unsigned any = __ballot_sync(0xFFFFFFFFu, probe != 0);
    const int is64 = (any == 0);

    double local = 0.0;

    if (n4 == 128) {
        for (int row = warp_in_blk * gridDim.x + blockIdx.x; row < B; row += nwarps) {
            // phase 0: label + all x loads issued back-to-back
            long long li = is64 ? ldg_persist_s64((const long long*)labels_raw + row, pol)
                                : (long long)ldg_persist_s32(labels_raw + row, pol);
            const float4* __restrict__ xr =
                reinterpret_cast<const float4*>(x + (size_t)row * D);
            float4 a0 = ldg_persist4(xr + lane, pol);
            float4 a1 = ldg_persist4(xr + lane + 32, pol);
            float4 a2 = ldg_persist4(xr + lane + 64, pol);
            float4 a3 = ldg_persist4(xr + lane + 96, pol);

            if (li < 0) li = 0;
            if (li >= C) li = C - 1;

            // phase 1: center loads back-to-back
            const float4* __restrict__ cr =
                reinterpret_cast<const float4*>(centers + (size_t)li * D);
            float4 b0 = ldg_persist4(cr + lane, pol);
            float4 b1 = ldg_persist4(cr + lane + 32, pol);
            float4 b2 = ldg_persist4(cr + lane + 64, pol);
            float4 b3 = ldg_persist4(cr + lane + 96, pol);

            // x-norm overlaps the center round-trip
            float xsq = 0.f;
            xsq = fmaf(a0.x, a0.x, fmaf(a0.y, a0.y, fmaf(a0.z, a0.z, fmaf(a0.w, a0.w, xsq))));
            xsq = fmaf(a1.x, a1.x, fmaf(a1.y, a1.y, fmaf(a1.z, a1.z, fmaf(a1.w, a1.w, xsq))));
            xsq = fmaf(a2.x, a2.x, fmaf(a2.y, a2.y, fmaf(a2.z, a2.z, fmaf(a2.w, a2.w, xsq))));
            xsq = fmaf(a3.x, a3.x, fmaf(a3.y, a3.y, fmaf(a3.z, a3.z, fmaf(a3.w, a3.w, xsq))));

            float dot = 0.f, csq = 0.f;
            dot = fmaf(a0.x, b0.x, fmaf(a0.y, b0.y, fmaf(a0.z, b0.z, fmaf(a0.w, b0.w, dot))));
            csq = fmaf(b0.x, b0.x, fmaf(b0.y, b0.y, fmaf(b0.z, b0.z, fmaf(b0.w, b0.w, csq))));
            dot = fmaf(a1.x, b1.x, fmaf(a1.y, b1.y, fmaf(a1.z, b1.z, fmaf(a1.w, b1.w, dot))));
            csq = fmaf(b1.x, b1.x, fmaf(b1.y, b1.y, fmaf(b1.z, b1.z, fmaf(b1.w, b1.w, csq))));
            dot = fmaf(a2.x, b2.x, fmaf(a2.y, b2.y, fmaf(a2.z, b2.z, fmaf(a2.w, b2.w, dot))));
            csq = fmaf(b2.x, b2.x, fmaf(b2.y, b2.y, fmaf(b2.z, b2.z, fmaf(b2.w, b2.w, csq))));
            dot = fmaf(a3.x, b3.x, fmaf(a3.y, b3.y, fmaf(a3.z, b3.z, fmaf(a3.w, b3.w, dot))));
            csq = fmaf(b3.x, b3.x, fmaf(b3.y, b3.y, fmaf(b3.z, b3.z, fmaf(b3.w, b3.w, csq))));

            float v = fmaf(0.3f, dot, 0.5f * (xsq + csq));
            #pragma unroll
            for (int o = 16; o > 0; o >>= 1)
                v += __shfl_down_sync(0xFFFFFFFFu, v, o);
            if (lane == 0) {
                v = fminf(fmaxf(v, 1e-12f), 1e12f);
                local += (double)v;
            }
        }
    } else {
        for (int row = warp_in_blk * gridDim.x + blockIdx.x; row < B; row += nwarps) {
            long long li = is64 ? ((const long long*)labels_raw)[row]
                                : (long long)labels_raw[row];
            if (li < 0) li = 0;
            if (li >= C) li = C - 1;
            const float4* xr = reinterpret_cast<const float4*>(x + (size_t)row * D);
            const float4* cr = reinterpret_cast<const float4*>(centers + (size_t)li * D);
            float dot = 0.f, xsq = 0.f, csq = 0.f;
            for (int i = lane; i < n4; i += 32) {
                float4 a = ldg_persist4(xr + i, pol);
                float4 b = ldg_persist4(cr + i, pol);
                dot = fmaf(a.x, b.x, fmaf(a.y, b.y, fmaf(a.z, b.z, fmaf(a.w, b.w, dot))));
                xsq = fmaf(a.x, a.x, fmaf(a.y, a.y, fmaf(a.z, a.z, fmaf(a.w, a.w, xsq))));
                csq = fmaf(b.x, b.x, fmaf(b.y, b.y, fmaf(b.z, b.z, fmaf(b.w, b.w, csq))));
            }
            float v = fmaf(0.3f, dot, 0.5f * (xsq + csq));
            #pragma unroll
            for (int o = 16; o > 0; o >>= 1)
                v += __shfl_down_sync(0xFFFFFFFFu, v, o);
            if (lane == 0) {
                v = fminf(fmaxf(v, 1e-12f), 1e12f);
                local += (double)v;
            }
        }
    }

    // ---- sync-free tail: per-warp accum atomic + release counter ----
    if (lane == 0) {
        if (local != 0.0) atomicAdd(&g_accum, local);
        unsigned int prev = atom_inc_release(&g_done_count);
        if (prev == (unsigned)nwarps - 1u) {
            // globally last warp: all accum adds are ordered-before by release
            double acc = ld_acquire_f64(&g_accum);
            double masked_zeros = ((double)B * (double)C - (double)B) * 1e-12;
            out[0] = (float)((acc + masked_zeros) / (double)B);
            // reset for next graph replay (visible at kernel completion)
            g_accum = 0.0;
            g_done_count = 0;
        }
    }
}

extern "C" void kernel_launch(void* const* d_in, const int* in_sizes, int n_in,
                              void* d_out, int out_size) {
    const float* x = (const float*)d_in[0];
    const float* centers = (const float*)d_in[1];
    const int* labels = (const int*)d_in[2];
    float* out = (float*)d_out;

    const int B = in_sizes[2];
    const int D = in_sizes[0] / B;
    const int C = in_sizes[1] / D;

    const int threads = 896;   // 28 warps, 1 CTA per SM
    const int blocks = 148;    // one per SM; transposed row mapping inside
    center_loss_fused<<<blocks, threads>>>(x, centers, labels, out, B, D, C);
}

// round 13
// speedup vs baseline: 1.4582x; 1.4582x over previous
#include <cuda_runtime.h>
#include <cstdint>

__device__ double g_accum = 0.0;
__device__ unsigned int g_done_count = 0;

__device__ __forceinline__ unsigned long long mk_evict_last_policy() {
    unsigned long long pol;
    asm volatile("createpolicy.fractional.L2::evict_last.b64 %0, 1.0;" : "=l"(pol));
    return pol;
}
__device__ __forceinline__ float4 ldg_persist4(const float4* p, unsigned long long pol) {
    float4 v;
    asm volatile("ld.global.L2::cache_hint.v4.f32 {%0,%1,%2,%3}, [%4], %5;"
                 : "=f"(v.x), "=f"(v.y), "=f"(v.z), "=f"(v.w)
                 : "l"(p), "l"(pol));
    return v;
}
__device__ __forceinline__ int ldg_persist_s32(const int* p, unsigned long long pol) {
    int v;
    asm volatile("ld.global.L2::cache_hint.s32 %0, [%1], %2;"
                 : "=r"(v) : "l"(p), "l"(pol));
    return v;
}
__device__ __forceinline__ long long ldg_persist_s64(const long long* p, unsigned long long pol) {
    long long v;
    asm volatile("ld.global.L2::cache_hint.s64 %0, [%1], %2;"
                 : "=l"(v) : "l"(p), "l"(pol));
    return v;
}

// One warp per row, transposed mapping across 148 SMs, loads evict_last.
// Tail (R11 structure): smem block reduce -> ONE double atomicAdd per block
// -> threadfence counter -> last block finalizes. 148 same-address atomics.
__global__ void __launch_bounds__(896, 1)
center_loss_fused(const float* __restrict__ x,
                  const float* __restrict__ centers,
                  const int* __restrict__ labels_raw,
                  float* __restrict__ out,
                  int B, int D, int C) {
    const int lane = threadIdx.x & 31;
    const int warp_in_blk = threadIdx.x >> 5;
    const int warps_per_blk = blockDim.x >> 5;
    const int nwarps = gridDim.x * warps_per_blk;
    const int n4 = D >> 2;

    const unsigned long long pol = mk_evict_last_policy();

    // dtype probe once per warp (int64 iff all odd int32 words are zero)
    int nsample = B < 32 ? B : 32;
    int probe = (lane < nsample) ? ldg_persist_s32(labels_raw + 2 * lane + 1, pol) : 0;
    unsigned any = __ballot_sync(0xFFFFFFFFu, probe != 0);
    const int is64 = (any == 0);

    double local = 0.0;

    if (n4 == 128) {
        for (int row = warp_in_blk * gridDim.x + blockIdx.x; row < B; row += nwarps) {
            // phase 0: label (resolved width only) + all x loads back-to-back
            long long li = is64 ? ldg_persist_s64((const long long*)labels_raw + row, pol)
                                : (long long)ldg_persist_s32(labels_raw + row, pol);
            const float4* __restrict__ xr =
                reinterpret_cast<const float4*>(x + (size_t)row * D);
            float4 a0 = ldg_persist4(xr + lane, pol);
            float4 a1 = ldg_persist4(xr + lane + 32, pol);
            float4 a2 = ldg_persist4(xr + lane + 64, pol);
            float4 a3 = ldg_persist4(xr + lane + 96, pol);

            if (li < 0) li = 0;
            if (li >= C) li = C - 1;

            // phase 1: center loads back-to-back
            const float4* __restrict__ cr =
                reinterpret_cast<const float4*>(centers + (size_t)li * D);
            float4 b0 = ldg_persist4(cr + lane, pol);
            float4 b1 = ldg_persist4(cr + lane + 32, pol);
            float4 b2 = ldg_persist4(cr + lane + 64, pol);
            float4 b3 = ldg_persist4(cr + lane + 96, pol);

            // x-norm overlaps the center round-trip
            float xsq = 0.f;
            xsq = fmaf(a0.x, a0.x, fmaf(a0.y, a0.y, fmaf(a0.z, a0.z, fmaf(a0.w, a0.w, xsq))));
            xsq = fmaf(a1.x, a1.x, fmaf(a1.y, a1.y, fmaf(a1.z, a1.z, fmaf(a1.w, a1.w, xsq))));
            xsq = fmaf(a2.x, a2.x, fmaf(a2.y, a2.y, fmaf(a2.z, a2.z, fmaf(a2.w, a2.w, xsq))));
            xsq = fmaf(a3.x, a3.x, fmaf(a3.y, a3.y, fmaf(a3.z, a3.z, fmaf(a3.w, a3.w, xsq))));

            float dot = 0.f, csq = 0.f;
            dot = fmaf(a0.x, b0.x, fmaf(a0.y, b0.y, fmaf(a0.z, b0.z, fmaf(a0.w, b0.w, dot))));
            csq = fmaf(b0.x, b0.x, fmaf(b0.y, b0.y, fmaf(b0.z, b0.z, fmaf(b0.w, b0.w, csq))));
            dot = fmaf(a1.x, b1.x, fmaf(a1.y, b1.y, fmaf(a1.z, b1.z, fmaf(a1.w, b1.w, dot))));
            csq = fmaf(b1.x, b1.x, fmaf(b1.y, b1.y, fmaf(b1.z, b1.z, fmaf(b1.w, b1.w, csq))));
            dot = fmaf(a2.x, b2.x, fmaf(a2.y, b2.y, fmaf(a2.z, b2.z, fmaf(a2.w, b2.w, dot))));
            csq = fmaf(b2.x, b2.x, fmaf(b2.y, b2.y, fmaf(b2.z, b2.z, fmaf(b2.w, b2.w, csq))));
            dot = fmaf(a3.x, b3.x, fmaf(a3.y, b3.y, fmaf(a3.z, b3.z, fmaf(a3.w, b3.w, dot))));
            csq = fmaf(b3.x, b3.x, fmaf(b3.y, b3.y, fmaf(b3.z, b3.z, fmaf(b3.w, b3.w, csq))));

            float v = fmaf(0.3f, dot, 0.5f * (xsq + csq));
            #pragma unroll
            for (int o = 16; o > 0; o >>= 1)
                v += __shfl_down_sync(0xFFFFFFFFu, v, o);
            if (lane == 0) {
                v = fminf(fmaxf(v, 1e-12f), 1e12f);
                local += (double)v;
            }
        }
    } else {
        for (int row = warp_in_blk * gridDim.x + blockIdx.x; row < B; row += nwarps) {
            long long li = is64 ? ((const long long*)labels_raw)[row]
                                : (long long)labels_raw[row];
            if (li < 0) li = 0;
            if (li >= C) li = C - 1;
            const float4* xr = reinterpret_cast<const float4*>(x + (size_t)row * D);
            const float4* cr = reinterpret_cast<const float4*>(centers + (size_t)li * D);
            float dot = 0.f, xsq = 0.f, csq = 0.f;
            for (int i = lane; i < n4; i += 32) {
                float4 a = ldg_persist4(xr + i, pol);
                float4 b = ldg_persist4(cr + i, pol);
                dot = fmaf(a.x, b.x, fmaf(a.y, b.y, fmaf(a.z, b.z, fmaf(a.w, b.w, dot))));
                xsq = fmaf(a.x, a.x, fmaf(a.y, a.y, fmaf(a.z, a.z, fmaf(a.w, a.w, xsq))));
                csq = fmaf(b.x, b.x, fmaf(b.y, b.y, fmaf(b.z, b.z, fmaf(b.w, b.w, csq))));
            }
            float v = fmaf(0.3f, dot, 0.5f * (xsq + csq));
            #pragma unroll
            for (int o = 16; o > 0; o >>= 1)
                v += __shfl_down_sync(0xFFFFFFFFu, v, o);
            if (lane == 0) {
                v = fminf(fmaxf(v, 1e-12f), 1e12f);
                local += (double)v;
            }
        }
    }

    // ---- block partial -> single global double atomic (R11 tail) ----
    __shared__ double sdata[32];
    if (lane == 0) sdata[warp_in_blk] = local;
    __syncthreads();
    if (warp_in_blk == 0) {
        double s = (lane < warps_per_blk) ? sdata[lane] : 0.0;
        #pragma unroll
        for (int o = 16; o > 0; o >>= 1)
            s += __shfl_down_sync(0xFFFFFFFFu, s, o);
        if (lane == 0) atomicAdd(&g_accum, s);
    }

    // ---- last block finalizes ----
    __shared__ bool s_last;
    __threadfence();
    if (threadIdx.x == 0) {
        unsigned int prev = atomicAdd(&g_done_count, 1u);
        s_last = (prev == gridDim.x - 1);
    }
    __syncthreads();
    if (s_last && threadIdx.x == 0) {
        double acc = atomicAdd(&g_accum, 0.0);   // coherent read at L2
        double masked_zeros = ((double)B * (double)C - (double)B) * 1e-12;
        out[0] = (float)((acc + masked_zeros) / (double)B);
        g_accum = 0.0;                            // reset for graph replay
        __threadfence();
        g_done_count = 0;
    }
}

extern "C" void kernel_launch(void* const* d_in, const int* in_sizes, int n_in,
                              void* d_out, int out_size) {
    const float* x = (const float*)d_in[0];
    const float* centers = (const float*)d_in[1];
    const int* labels = (const int*)d_in[2];
    float* out = (float*)d_out;

    const int B = in_sizes[2];
    const int D = in_sizes[0] / B;
    const int C = in_sizes[1] / D;

    const int threads = 896;   // 28 warps, 1 CTA per SM
    const int blocks = 148;    // one per SM; transposed row mapping inside
    center_loss_fused<<<blocks, threads>>>(x, centers, labels, out, B, D, C);
}

// round 14
// speedup vs baseline: 1.7316x; 1.1875x over previous
#include <cuda_runtime.h>
#include <cstdint>

__device__ double g_accum = 0.0;
__device__ unsigned int g_done_count = 0;

__device__ __forceinline__ unsigned long long mk_evict_last_policy() {
    unsigned long long pol;
    asm volatile("createpolicy.fractional.L2::evict_last.b64 %0, 1.0;" : "=l"(pol));
    return pol;
}
__device__ __forceinline__ float4 ldg_persist4(const float4* p, unsigned long long pol) {
    float4 v;
    asm volatile("ld.global.L2::cache_hint.v4.f32 {%0,%1,%2,%3}, [%4], %5;"
                 : "=f"(v.x), "=f"(v.y), "=f"(v.z), "=f"(v.w)
                 : "l"(p), "l"(pol));
    return v;
}
__device__ __forceinline__ int ldg_persist_s32(const int* p, unsigned long long pol) {
    int v;
    asm volatile("ld.global.L2::cache_hint.s32 %0, [%1], %2;"
                 : "=r"(v) : "l"(p), "l"(pol));
    return v;
}
__device__ __forceinline__ long long ldg_persist_s64(const long long* p, unsigned long long pol) {
    long long v;
    asm volatile("ld.global.L2::cache_hint.s64 %0, [%1], %2;"
                 : "=l"(v) : "l"(p), "l"(pol));
    return v;
}

// R11 structure (measured best: 8.99us): one warp per row, transposed mapping
// across 148 SMs, evict_last on all loads, SPECULATIVE dual-width label load
// (both LDGs issued unconditionally, selected after ballot), smem block
// reduce -> ONE double atomicAdd per block -> threadfence counter tail.
__global__ void __launch_bounds__(896, 1)
center_loss_fused(const float* __restrict__ x,
                  const float* __restrict__ centers,
                  const int* __restrict__ labels_raw,
                  float* __restrict__ out,
                  int B, int D, int C) {
    const int lane = threadIdx.x & 31;
    const int warp_in_blk = threadIdx.x >> 5;
    const int warps_per_blk = blockDim.x >> 5;
    const int nwarps = gridDim.x * warps_per_blk;
    const int n4 = D >> 2;

    const unsigned long long pol = mk_evict_last_policy();

    // dtype probe once per warp (independent of everything below)
    int nsample = B < 32 ? B : 32;
    int probe = (lane < nsample) ? ldg_persist_s32(labels_raw + 2 * lane + 1, pol) : 0;

    double local = 0.0;

    if (n4 == 128) {
        for (int row = warp_in_blk * gridDim.x + blockIdx.x; row < B; row += nwarps) {
            // phase 0: all independent loads back-to-back (speculative labels)
            int cand32 = ldg_persist_s32(labels_raw + row, pol);
            long long cand64 = ldg_persist_s64((const long long*)labels_raw + row, pol);
            const float4* __restrict__ xr =
                reinterpret_cast<const float4*>(x + (size_t)row * D);
            float4 a0 = ldg_persist4(xr + lane, pol);
            float4 a1 = ldg_persist4(xr + lane + 32, pol);
            float4 a2 = ldg_persist4(xr + lane + 64, pol);
            float4 a3 = ldg_persist4(xr + lane + 96, pol);

            // phase 1: resolve label dtype while x streams in
            unsigned any = __ballot_sync(0xFFFFFFFFu, probe != 0);
            long long li = (any == 0) ? cand64 : (long long)cand32;
            if (li < 0) li = 0;
            if (li >= C) li = C - 1;

            // phase 2: center loads back-to-back
            const float4* __restrict__ cr =
                reinterpret_cast<const float4*>(centers + (size_t)li * D);
            float4 b0 = ldg_persist4(cr + lane, pol);
            float4 b1 = ldg_persist4(cr + lane + 32, pol);
            float4 b2 = ldg_persist4(cr + lane + 64, pol);
            float4 b3 = ldg_persist4(cr + lane + 96, pol);

            // x-norm overlaps the center round-trip
            float xsq = 0.f;
            xsq = fmaf(a0.x, a0.x, fmaf(a0.y, a0.y, fmaf(a0.z, a0.z, fmaf(a0.w, a0.w, xsq))));
            xsq = fmaf(a1.x, a1.x, fmaf(a1.y, a1.y, fmaf(a1.z, a1.z, fmaf(a1.w, a1.w, xsq))));
            xsq = fmaf(a2.x, a2.x, fmaf(a2.y, a2.y, fmaf(a2.z, a2.z, fmaf(a2.w, a2.w, xsq))));
            xsq = fmaf(a3.x, a3.x, fmaf(a3.y, a3.y, fmaf(a3.z, a3.z, fmaf(a3.w, a3.w, xsq))));

            float dot = 0.f, csq = 0.f;
            dot = fmaf(a0.x, b0.x, fmaf(a0.y, b0.y, fmaf(a0.z, b0.z, fmaf(a0.w, b0.w, dot))));
            csq = fmaf(b0.x, b0.x, fmaf(b0.y, b0.y, fmaf(b0.z, b0.z, fmaf(b0.w, b0.w, csq))));
            dot = fmaf(a1.x, b1.x, fmaf(a1.y, b1.y, fmaf(a1.z, b1.z, fmaf(a1.w, b1.w, dot))));
            csq = fmaf(b1.x, b1.x, fmaf(b1.y, b1.y, fmaf(b1.z, b1.z, fmaf(b1.w, b1.w, csq))));
            dot = fmaf(a2.x, b2.x, fmaf(a2.y, b2.y, fmaf(a2.z, b2.z, fmaf(a2.w, b2.w, dot))));
            csq = fmaf(b2.x, b2.x, fmaf(b2.y, b2.y, fmaf(b2.z, b2.z, fmaf(b2.w, b2.w, csq))));
            dot = fmaf(a3.x, b3.x, fmaf(a3.y, b3.y, fmaf(a3.z, b3.z, fmaf(a3.w, b3.w, dot))));
            csq = fmaf(b3.x, b3.x, fmaf(b3.y, b3.y, fmaf(b3.z, b3.z, fmaf(b3.w, b3.w, csq))));

            float v = fmaf(0.3f, dot, 0.5f * (xsq + csq));
            #pragma unroll
            for (int o = 16; o > 0; o >>= 1)
                v += __shfl_down_sync(0xFFFFFFFFu, v, o);
            if (lane == 0) {
                v = fminf(fmaxf(v, 1e-12f), 1e12f);
                local += (double)v;
            }
        }
    } else {
        unsigned any0 = __ballot_sync(0xFFFFFFFFu, probe != 0);
        const int is64 = (any0 == 0);
        for (int row = warp_in_blk * gridDim.x + blockIdx.x; row < B; row += nwarps) {
            long long li = is64 ? ((const long long*)labels_raw)[row]
                                : (long long)labels_raw[row];
            if (li < 0) li = 0;
            if (li >= C) li = C - 1;
            const float4* xr = reinterpret_cast<const float4*>(x + (size_t)row * D);
            const float4* cr = reinterpret_cast<const float4*>(centers + (size_t)li * D);
            float dot = 0.f, xsq = 0.f, csq = 0.f;
            for (int i = lane; i < n4; i += 32) {
                float4 a = ldg_persist4(xr + i, pol);
                float4 b = ldg_persist4(cr + i, pol);
                dot = fmaf(a.x, b.x, fmaf(a.y, b.y, fmaf(a.z, b.z, fmaf(a.w, b.w, dot))));
                xsq = fmaf(a.x, a.x, fmaf(a.y, a.y, fmaf(a.z, a.z, fmaf(a.w, a.w, xsq))));
                csq = fmaf(b.x, b.x, fmaf(b.y, b.y, fmaf(b.z, b.z, fmaf(b.w, b.w, csq))));
            }
            float v = fmaf(0.3f, dot, 0.5f * (xsq + csq));
            #pragma unroll
            for (int o = 16; o > 0; o >>= 1)
                v += __shfl_down_sync(0xFFFFFFFFu, v, o);
            if (lane == 0) {
                v = fminf(fmaxf(v, 1e-12f), 1e12f);
                local += (double)v;
            }
        }
    }

    // ---- block partial -> single global double atomic ----
    __shared__ double sdata[32];
    if (lane == 0) sdata[warp_in_blk] = local;
    __syncthreads();
    if (warp_in_blk == 0) {
        double s = (lane < warps_per_blk) ? sdata[lane] : 0.0;
        #pragma unroll
        for (int o = 16; o > 0; o >>= 1)
            s += __shfl_down_sync(0xFFFFFFFFu, s, o);
        if (lane == 0) atomicAdd(&g_accum, s);
    }

    // ---- last block finalizes: one load, one store ----
    __shared__ bool s_last;
    __threadfence();
    if (threadIdx.x == 0) {
        unsigned int prev = atomicAdd(&g_done_count, 1u);
        s_last = (prev == gridDim.x - 1);
    }
    __syncthreads();
    if (s_last && threadIdx.x == 0) {
        double acc = atomicAdd(&g_accum, 0.0);      // coherent read at L2
        double masked_zeros = ((double)B * (double)C - (double)B) * 1e-12;
        out[0] = (float)((acc + masked_zeros) / (double)B);
        g_accum = 0.0;                               // reset for graph replay
        __threadfence();
        g_done_count = 0;
    }
}

extern "C" void kernel_launch(void* const* d_in, const int* in_sizes, int n_in,
                              void* d_out, int out_size) {
    const float* x = (const float*)d_in[0];
    const float* centers = (const float*)d_in[1];
    const int* labels = (const int*)d_in[2];
    float* out = (float*)d_out;

    const int B = in_sizes[2];
    const int D = in_sizes[0] / B;
    const int C = in_sizes[1] / D;

    const int threads = 896;   // 28 warps, 1 CTA per SM
    const int blocks = 148;    // one per SM; transposed row mapping inside
    center_loss_fused<<<blocks, threads>>>(x, centers, labels, out, B, D, C);
}